// round 16
// baseline (speedup 1.0000x reference)
#include <cuda_runtime.h>
#include <stdint.h>

#define HH 1024
#define WW 2048
#define HW (HH * WW)              // 2,097,152 pixels
#define NI 128                    // instances
#define NB 10                     // "thing" classes 24..33
#define NBINS (NI * NB)           // 1280
#define THREADS 256
#define NGRP (HW / 4)             // 524,288 float4 groups per channel

// stats geometry: 8 px per thread == one 32B output sector per thread
#define NSECT (HW / 8)                       // 262,144 sectors
#define NBLK_STATS (NSECT / THREADS)         // 1024 stats blocks

// fill geometry: each thread stores 8 float4 (128B), strided for coalescing
#define FPT 8
#define NQ ((size_t)NI * HW / 4)             // float4 count of mask region
#define NBLK_FILL ((int)(NQ / (THREADS * FPT)))   // 32,768 fill blocks
#define NBLK_A (NBLK_STATS + NBLK_FILL)

// bucketed worklist: one bucket per instance id (~4.8K expected, 64K cap)
#define BCAP 65536
#define BPB 32                               // C blocks per bucket
#define NBLK_C (NI * BPB)                    // 4096 C blocks

// Scratch (no cudaMalloc). Zero-initialized at load.
// Reset protocol per run: g_bcount/g_counts/g_isum/g_done reset by C's
// ticket block. Bucket contents never need cleaning (C reads only
// [0, count)). Deterministic across graph replays.
__device__ unsigned int g_buckets[NI * BCAP];   // (sec<<8)|mask, id implicit
__device__ int          g_bcount[NI];
__device__ int          g_counts[NBINS];
__device__ float        g_isum[NI];
__device__ unsigned int g_done;

// ---------------------------------------------------------------------------
// Kernel A: fused zero-fill + counts + bucketed worklist. NO prob reads.
//   blocks [0, 1024): stats — 8 px (= 1 output sector) per thread:
//     count histogram -> RED; per distinct id in sector: append (sec,mask)
//     to bucket[id-1] via 3-phase shared counting.
//   blocks [1024, NBLK_A): fill — 8 strided float4 streaming stores per
//     thread (128B): dependency-free store stream, minimal CTA count.
// ---------------------------------------------------------------------------
__global__ void __launch_bounds__(THREADS)
fill_stats_kernel(const int4* __restrict__ seg4,
                  const int4* __restrict__ inst4,
                  float4*     __restrict__ out4) {
    const int tid = threadIdx.x;
    const int b   = blockIdx.x;

    if (b >= NBLK_STATS) {
        // ---------------- fill path: 8 coalesced streaming stores ---------
        const size_t base = (size_t)(b - NBLK_STATS) * (THREADS * FPT) + tid;
        const float4 z = make_float4(0.f, 0.f, 0.f, 0.f);
        #pragma unroll
        for (int k = 0; k < FPT; ++k)
            __stcs(&out4[base + (size_t)k * THREADS], z);
        return;
    }

    // -------------------- stats path ------------------------------------
    __shared__ int s_cnt[NBINS];
    __shared__ int s_bcnt[NI];     // phase-1 per-id entry counts
    __shared__ int s_base[NI];     // reserved global base per id
    __shared__ int s_boff[NI];     // phase-2 running offsets

    for (int i = tid; i < NBINS; i += THREADS) s_cnt[i] = 0;
    if (tid < NI) { s_bcnt[tid] = 0; s_boff[tid] = 0; }
    __syncthreads();

    const int t = b * THREADS + tid;            // sector index (8 px)

    const int4 sgA = seg4[2 * t];
    const int4 sgB = seg4[2 * t + 1];
    const int4 imA = inst4[2 * t];
    const int4 imB = inst4[2 * t + 1];
    const int ss[8] = { sgA.x, sgA.y, sgA.z, sgA.w, sgB.x, sgB.y, sgB.z, sgB.w };
    const int iv[8] = { imA.x, imA.y, imA.z, imA.w, imB.x, imB.y, imB.z, imB.w };
    int ids[8];
    int any = 0;

    #pragma unroll
    for (int j = 0; j < 8; ++j) {
        const int s  = ss[j];
        const int id = (s >= 24 && s <= 33) ? iv[j] : 0;
        ids[j] = id;
        any |= id;
        if (id > 0)
            atomicAdd(&s_cnt[(id - 1) * NB + (s - 24)], 1);
    }

    // local distinct-id entries for this sector
    int          lid[8];
    unsigned int lent[8];
    int ln = 0;
    if (any) {
        #pragma unroll
        for (int j = 0; j < 8; ++j) {
            const int id = ids[j];
            if (id == 0) continue;
            bool first = true;
            #pragma unroll
            for (int k = 0; k < 8; ++k)
                if (k < j && ids[k] == id) first = false;
            if (first) {
                unsigned int mask = 0;
                #pragma unroll
                for (int k = 0; k < 8; ++k)
                    if (k >= j && ids[k] == id) mask |= 1u << k;
                lid[ln]  = id - 1;
                lent[ln] = ((unsigned int)t << 8) | mask;
                ++ln;
            }
        }
        for (int e = 0; e < ln; ++e)
            atomicAdd(&s_bcnt[lid[e]], 1);          // phase 1: count
    }

    __syncthreads();
    if (tid < NI) {
        const int c = s_bcnt[tid];
        s_base[tid] = c ? atomicAdd(&g_bcount[tid], c) : 0;
    }
    __syncthreads();

    for (int e = 0; e < ln; ++e) {                  // phase 2: place
        const int i  = lid[e];
        const int o  = atomicAdd(&s_boff[i], 1);
        g_buckets[(size_t)i * BCAP + s_base[i] + o] = lent[e];
    }

    for (int i = tid; i < NBINS; i += THREADS) {
        const int cv = s_cnt[i];
        if (cv) atomicAdd(&g_counts[i], cv);
    }
}

// ---------------------------------------------------------------------------
// Kernel C: per-instance bucketed scatter+gather + ticketed finalize.
//   block = (bucket, j): works ONLY instance `bucket` ->
//     - one-hot writes confined to one 8MB channel
//     - argmax class computed ONCE per block; gathers confined to one
//       8MB prob channel
//     - per-thread accumulation -> block reduce -> ONE atomicAdd
//   BPB=32: ~150 entries per block -> finer wave granularity, better
//   tail-latency pipelining than R15's 2-wave shape.
//   Last block (ticket among all NBLK_C): tail outputs + all scratch resets.
// ---------------------------------------------------------------------------
__global__ void __launch_bounds__(THREADS)
scatter_gather_kernel(const float4* __restrict__ probs4,
                      const float*  __restrict__ inst_probs,
                      float*        __restrict__ out) {
    const int tid    = threadIdx.x;
    const int bucket = blockIdx.x / BPB;
    const int j      = blockIdx.x % BPB;

    __shared__ int          s_cls;
    __shared__ float        s_wsum[THREADS / 32];
    __shared__ unsigned int s_ticket;

    const int n = g_bcount[bucket];

    if (tid == 0) {
        int best = 0, bestc = 0;
        #pragma unroll
        for (int c = 0; c < NB; ++c) {
            const int v = g_counts[bucket * NB + c];
            if (v > best) { best = v; bestc = c; }   // first-occurrence ties
        }
        s_cls = 24 + bestc;
    }
    __syncthreads();
    const int cls = s_cls;

    // this block's contiguous chunk of the bucket
    const int chunk = (n + BPB - 1) / BPB;
    const int start = j * chunk;
    const int end   = (start + chunk < n) ? (start + chunk) : n;

    const unsigned int* bkt = &g_buckets[(size_t)bucket * BCAP];
    float*              och = out + (size_t)bucket * HW;
    const float4*       pch = probs4 + (size_t)cls * NGRP;

    float acc = 0.0f;
    for (int i = start + tid; i < end; i += THREADS) {
        const unsigned int e    = __ldcs(&bkt[i]);   // streaming: don't pollute L2
        const unsigned int sec  = e >> 8;
        const unsigned int mask = e & 0xFFu;

        float4 lo, hi;
        lo.x = (mask & 0x01u) ? 1.0f : 0.0f;
        lo.y = (mask & 0x02u) ? 1.0f : 0.0f;
        lo.z = (mask & 0x04u) ? 1.0f : 0.0f;
        lo.w = (mask & 0x08u) ? 1.0f : 0.0f;
        hi.x = (mask & 0x10u) ? 1.0f : 0.0f;
        hi.y = (mask & 0x20u) ? 1.0f : 0.0f;
        hi.z = (mask & 0x40u) ? 1.0f : 0.0f;
        hi.w = (mask & 0x80u) ? 1.0f : 0.0f;
        float4* dst = (float4*)(och + (size_t)sec * 8);
        __stcs(&dst[0], lo);
        __stcs(&dst[1], hi);

        const float4 pa = __ldg(&pch[(size_t)sec * 2]);
        const float4 pb = __ldg(&pch[(size_t)sec * 2 + 1]);
        if (mask & 0x01u) acc += pa.x;
        if (mask & 0x02u) acc += pa.y;
        if (mask & 0x04u) acc += pa.z;
        if (mask & 0x08u) acc += pa.w;
        if (mask & 0x10u) acc += pb.x;
        if (mask & 0x20u) acc += pb.y;
        if (mask & 0x40u) acc += pb.z;
        if (mask & 0x80u) acc += pb.w;
    }

    // block reduce acc -> one global atomic
    #pragma unroll
    for (int o = 16; o > 0; o >>= 1)
        acc += __shfl_down_sync(0xFFFFFFFFu, acc, o);
    if ((tid & 31) == 0) s_wsum[tid >> 5] = acc;
    __syncthreads();
    if (tid == 0) {
        float bs = 0.0f;
        #pragma unroll
        for (int w = 0; w < THREADS / 32; ++w) bs += s_wsum[w];
        if (bs != 0.0f) atomicAdd(&g_isum[bucket], bs);
    }

    // ---- ticket; last block finalizes + resets ----
    __threadfence();
    __syncthreads();
    if (tid == 0)
        s_ticket = atomicAdd(&g_done, 1u);
    __syncthreads();

    if (s_ticket == (unsigned)(NBLK_C - 1)) {
        float* tail = out + (size_t)NI * HW;
        if (tid < NI) {
            int tot = 0, best = 0, bestc = 0;
            #pragma unroll
            for (int c = 0; c < NB; ++c) {
                const int v = __ldcg(&g_counts[tid * NB + c]);
                tot += v;
                if (v > best) { best = v; bestc = c; }
            }
            const int cl = (tot > 0) ? (24 + bestc) : 0;
            const float sum = __ldcg(&g_isum[tid]);
            tail[0 * NI + tid] = (float)cl;                     // inst_class
            tail[1 * NI + tid] = inst_probs[tid];               // instance_probs
            tail[2 * NI + tid] = (tot > 0) ? (sum / (float)tot) : 0.0f;
            tail[3 * NI + tid] = (float)tot;                    // total
            tail[4 * NI + tid] = (tot > 0) ? 1.0f : 0.0f;       // valid
        }
        __syncthreads();
        // reset all scratch for the next graph replay
        for (int k = tid; k < NBINS; k += THREADS) g_counts[k] = 0;
        if (tid < NI) { g_isum[tid] = 0.0f; g_bcount[tid] = 0; }
        if (tid == 0) g_done = 0u;
    }
}

// ---------------------------------------------------------------------------
extern "C" void kernel_launch(void* const* d_in, const int* in_sizes, int n_in,
                              void* d_out, int out_size) {
    const int*   seg    = (const int*)  d_in[0];   // (H, W) int32
    const int*   inst   = (const int*)  d_in[1];   // (H, W) int32
    const float* probs  = (const float*)d_in[2];   // (C, H, W) float32
    const float* iprobs = (const float*)d_in[3];   // (128,) float32
    float* out = (float*)d_out;

    fill_stats_kernel<<<NBLK_A, THREADS>>>(
        (const int4*)seg, (const int4*)inst, (float4*)out);
    scatter_gather_kernel<<<NBLK_C, THREADS>>>(
        (const float4*)probs, iprobs, out);
}

// round 17
// speedup vs baseline: 1.0241x; 1.0241x over previous
#include <cuda_runtime.h>
#include <stdint.h>

#define HH 1024
#define WW 2048
#define HW (HH * WW)              // 2,097,152 pixels
#define NI 128                    // instances
#define NB 10                     // "thing" classes 24..33
#define NBINS (NI * NB)           // 1280
#define THREADS 256
#define NGRP (HW / 4)             // 524,288 float4 groups per channel

// stats geometry: 8 px per thread == one 32B output sector per thread
#define NSECT (HW / 8)                       // 262,144 sectors
#define NBLK_STATS (NSECT / THREADS)         // 1024 stats blocks

// fill geometry: each thread stores 4 float4 (64B), strided for coalescing
#define FPT 4
#define NQ ((size_t)NI * HW / 4)             // float4 count of mask region
#define NBLK_FILL ((int)(NQ / (THREADS * FPT)))   // 65,536 fill blocks
#define NBLK_A (NBLK_STATS + NBLK_FILL)

// bucketed worklist: one bucket per instance id (~4.8K expected, 64K cap)
#define BCAP 65536
#define BPB 8                                // C blocks per bucket
#define NBLK_C (NI * BPB)                    // 1024 C blocks

// Scratch (no cudaMalloc). Zero-initialized at load.
// Reset protocol per run: g_bcount/g_counts/g_isum/g_done reset by C's
// ticket block. Bucket contents never need cleaning (C reads only
// [0, count)). Deterministic across graph replays.
__device__ unsigned int g_buckets[NI * BCAP];   // (sec<<8)|mask, id implicit
__device__ int          g_bcount[NI];
__device__ int          g_counts[NBINS];
__device__ float        g_isum[NI];
__device__ unsigned int g_done;

// ---------------------------------------------------------------------------
// Kernel A: fused zero-fill + counts + bucketed worklist. NO prob reads.
//   blocks [0, 1024): stats — 8 px (= 1 output sector) per thread:
//     count histogram -> RED; per distinct id in sector: append (sec,mask)
//     to bucket[id-1] via 3-phase shared counting.
//   blocks [1024, NBLK_A): fill — 4 strided float4 streaming stores per
//     thread (64B): dependency-free store stream -> DRAM write roofline.
// ---------------------------------------------------------------------------
__global__ void __launch_bounds__(THREADS)
fill_stats_kernel(const int4* __restrict__ seg4,
                  const int4* __restrict__ inst4,
                  float4*     __restrict__ out4) {
    const int tid = threadIdx.x;
    const int b   = blockIdx.x;

    if (b >= NBLK_STATS) {
        // ---------------- fill path: 4 coalesced streaming stores ---------
        const size_t base = (size_t)(b - NBLK_STATS) * (THREADS * FPT) + tid;
        const float4 z = make_float4(0.f, 0.f, 0.f, 0.f);
        #pragma unroll
        for (int k = 0; k < FPT; ++k)
            __stcs(&out4[base + (size_t)k * THREADS], z);
        return;
    }

    // -------------------- stats path ------------------------------------
    __shared__ int s_cnt[NBINS];
    __shared__ int s_bcnt[NI];     // phase-1 per-id entry counts
    __shared__ int s_base[NI];     // reserved global base per id
    __shared__ int s_boff[NI];     // phase-2 running offsets

    for (int i = tid; i < NBINS; i += THREADS) s_cnt[i] = 0;
    if (tid < NI) { s_bcnt[tid] = 0; s_boff[tid] = 0; }
    __syncthreads();

    const int t = b * THREADS + tid;            // sector index (8 px)

    const int4 sgA = seg4[2 * t];
    const int4 sgB = seg4[2 * t + 1];
    const int4 imA = inst4[2 * t];
    const int4 imB = inst4[2 * t + 1];
    const int ss[8] = { sgA.x, sgA.y, sgA.z, sgA.w, sgB.x, sgB.y, sgB.z, sgB.w };
    const int iv[8] = { imA.x, imA.y, imA.z, imA.w, imB.x, imB.y, imB.z, imB.w };
    int ids[8];
    int any = 0;

    #pragma unroll
    for (int j = 0; j < 8; ++j) {
        const int s  = ss[j];
        const int id = (s >= 24 && s <= 33) ? iv[j] : 0;
        ids[j] = id;
        any |= id;
        if (id > 0)
            atomicAdd(&s_cnt[(id - 1) * NB + (s - 24)], 1);
    }

    // local distinct-id entries for this sector
    int          lid[8];
    unsigned int lent[8];
    int ln = 0;
    if (any) {
        #pragma unroll
        for (int j = 0; j < 8; ++j) {
            const int id = ids[j];
            if (id == 0) continue;
            bool first = true;
            #pragma unroll
            for (int k = 0; k < 8; ++k)
                if (k < j && ids[k] == id) first = false;
            if (first) {
                unsigned int mask = 0;
                #pragma unroll
                for (int k = 0; k < 8; ++k)
                    if (k >= j && ids[k] == id) mask |= 1u << k;
                lid[ln]  = id - 1;
                lent[ln] = ((unsigned int)t << 8) | mask;
                ++ln;
            }
        }
        for (int e = 0; e < ln; ++e)
            atomicAdd(&s_bcnt[lid[e]], 1);          // phase 1: count
    }

    __syncthreads();
    if (tid < NI) {
        const int c = s_bcnt[tid];
        s_base[tid] = c ? atomicAdd(&g_bcount[tid], c) : 0;
    }
    __syncthreads();

    for (int e = 0; e < ln; ++e) {                  // phase 2: place
        const int i  = lid[e];
        const int o  = atomicAdd(&s_boff[i], 1);
        g_buckets[(size_t)i * BCAP + s_base[i] + o] = lent[e];
    }

    for (int i = tid; i < NBINS; i += THREADS) {
        const int cv = s_cnt[i];
        if (cv) atomicAdd(&g_counts[i], cv);
    }
}

// ---------------------------------------------------------------------------
// Kernel C: per-instance bucketed scatter+gather + ticketed finalize.
//   block = (bucket, j): works ONLY instance `bucket` ->
//     - one-hot writes confined to one 8MB channel
//     - argmax class computed ONCE per block; gathers confined to one
//       8MB prob channel
//     - per-thread accumulation -> block reduce -> ONE atomicAdd
//   BPB=8: ~600 entries per block -> 2-3 loop iterations per thread,
//   pipelining the roughly-ascending sector sequence for DRAM row reuse
//   and halving fixed per-block costs vs BPB=16.
//   Last block (ticket among all NBLK_C): tail outputs + all scratch resets.
// ---------------------------------------------------------------------------
__global__ void __launch_bounds__(THREADS)
scatter_gather_kernel(const float4* __restrict__ probs4,
                      const float*  __restrict__ inst_probs,
                      float*        __restrict__ out) {
    const int tid    = threadIdx.x;
    const int bucket = blockIdx.x / BPB;
    const int j      = blockIdx.x % BPB;

    __shared__ int          s_cls;
    __shared__ float        s_wsum[THREADS / 32];
    __shared__ unsigned int s_ticket;

    const int n = g_bcount[bucket];

    if (tid == 0) {
        int best = 0, bestc = 0;
        #pragma unroll
        for (int c = 0; c < NB; ++c) {
            const int v = g_counts[bucket * NB + c];
            if (v > best) { best = v; bestc = c; }   // first-occurrence ties
        }
        s_cls = 24 + bestc;
    }
    __syncthreads();
    const int cls = s_cls;

    // this block's contiguous chunk of the bucket
    const int chunk = (n + BPB - 1) / BPB;
    const int start = j * chunk;
    const int end   = (start + chunk < n) ? (start + chunk) : n;

    const unsigned int* bkt = &g_buckets[(size_t)bucket * BCAP];
    float*              och = out + (size_t)bucket * HW;
    const float4*       pch = probs4 + (size_t)cls * NGRP;

    float acc = 0.0f;
    for (int i = start + tid; i < end; i += THREADS) {
        const unsigned int e    = bkt[i];
        const unsigned int sec  = e >> 8;
        const unsigned int mask = e & 0xFFu;

        float4 lo, hi;
        lo.x = (mask & 0x01u) ? 1.0f : 0.0f;
        lo.y = (mask & 0x02u) ? 1.0f : 0.0f;
        lo.z = (mask & 0x04u) ? 1.0f : 0.0f;
        lo.w = (mask & 0x08u) ? 1.0f : 0.0f;
        hi.x = (mask & 0x10u) ? 1.0f : 0.0f;
        hi.y = (mask & 0x20u) ? 1.0f : 0.0f;
        hi.z = (mask & 0x40u) ? 1.0f : 0.0f;
        hi.w = (mask & 0x80u) ? 1.0f : 0.0f;
        float4* dst = (float4*)(och + (size_t)sec * 8);
        __stcs(&dst[0], lo);
        __stcs(&dst[1], hi);

        const float4 pa = __ldg(&pch[(size_t)sec * 2]);
        const float4 pb = __ldg(&pch[(size_t)sec * 2 + 1]);
        if (mask & 0x01u) acc += pa.x;
        if (mask & 0x02u) acc += pa.y;
        if (mask & 0x04u) acc += pa.z;
        if (mask & 0x08u) acc += pa.w;
        if (mask & 0x10u) acc += pb.x;
        if (mask & 0x20u) acc += pb.y;
        if (mask & 0x40u) acc += pb.z;
        if (mask & 0x80u) acc += pb.w;
    }

    // block reduce acc -> one global atomic
    #pragma unroll
    for (int o = 16; o > 0; o >>= 1)
        acc += __shfl_down_sync(0xFFFFFFFFu, acc, o);
    if ((tid & 31) == 0) s_wsum[tid >> 5] = acc;
    __syncthreads();
    if (tid == 0) {
        float bs = 0.0f;
        #pragma unroll
        for (int w = 0; w < THREADS / 32; ++w) bs += s_wsum[w];
        if (bs != 0.0f) atomicAdd(&g_isum[bucket], bs);
    }

    // ---- ticket; last block finalizes + resets ----
    __threadfence();
    __syncthreads();
    if (tid == 0)
        s_ticket = atomicAdd(&g_done, 1u);
    __syncthreads();

    if (s_ticket == (unsigned)(NBLK_C - 1)) {
        float* tail = out + (size_t)NI * HW;
        if (tid < NI) {
            int tot = 0, best = 0, bestc = 0;
            #pragma unroll
            for (int c = 0; c < NB; ++c) {
                const int v = __ldcg(&g_counts[tid * NB + c]);
                tot += v;
                if (v > best) { best = v; bestc = c; }
            }
            const int cl = (tot > 0) ? (24 + bestc) : 0;
            const float sum = __ldcg(&g_isum[tid]);
            tail[0 * NI + tid] = (float)cl;                     // inst_class
            tail[1 * NI + tid] = inst_probs[tid];               // instance_probs
            tail[2 * NI + tid] = (tot > 0) ? (sum / (float)tot) : 0.0f;
            tail[3 * NI + tid] = (float)tot;                    // total
            tail[4 * NI + tid] = (tot > 0) ? 1.0f : 0.0f;       // valid
        }
        __syncthreads();
        // reset all scratch for the next graph replay
        for (int k = tid; k < NBINS; k += THREADS) g_counts[k] = 0;
        if (tid < NI) { g_isum[tid] = 0.0f; g_bcount[tid] = 0; }
        if (tid == 0) g_done = 0u;
    }
}

// ---------------------------------------------------------------------------
extern "C" void kernel_launch(void* const* d_in, const int* in_sizes, int n_in,
                              void* d_out, int out_size) {
    const int*   seg    = (const int*)  d_in[0];   // (H, W) int32
    const int*   inst   = (const int*)  d_in[1];   // (H, W) int32
    const float* probs  = (const float*)d_in[2];   // (C, H, W) float32
    const float* iprobs = (const float*)d_in[3];   // (128,) float32
    float* out = (float*)d_out;

    fill_stats_kernel<<<NBLK_A, THREADS>>>(
        (const int4*)seg, (const int4*)inst, (float4*)out);
    scatter_gather_kernel<<<NBLK_C, THREADS>>>(
        (const float4*)probs, iprobs, out);
}